// round 2
// baseline (speedup 1.0000x reference)
#include <cuda_runtime.h>

#define M_GT_MAX 128

__global__ __launch_bounds__(256) void rpn_kernel(
    const float* __restrict__ anchors,
    const float* __restrict__ deltas,
    const float* __restrict__ gt,
    float* __restrict__ out,
    int N, int M)
{
    __shared__ float4 s_box[M_GT_MAX];
    __shared__ float  s_area[M_GT_MAX];

    const float SCALE_CLAMP = 3.3322045f;   // log(224/8)
    const float IOU_LOW  = 0.3f;
    const float IOU_HIGH = 0.6f;
    const float NEUTRAL  = -100000000.0f;

    int t = threadIdx.x;

    // Stage GT boxes into shared memory. Invalid GTs (cls == -1) become
    // degenerate far-away boxes: IoU with any anchor is exactly 0. The
    // reference assigns -1.0 to invalid columns; since any anchor whose max
    // is <= 0 (including 0 vs -1 ambiguity) gets its matched row overwritten
    // with -1.0, the final outputs are identical (proof in analysis).
    if (t < M) {
        float gx1 = gt[t * 5 + 0];
        float gy1 = gt[t * 5 + 1];
        float gx2 = gt[t * 5 + 2];
        float gy2 = gt[t * 5 + 3];
        float cls = gt[t * 5 + 4];
        // area2 with reference rounding: (x2-x1)*(y2-y1), each op rounded
        float area = __fmul_rn(__fsub_rn(gx2, gx1), __fsub_rn(gy2, gy1));
        if (cls == -1.0f) {
            gx1 = gy1 = gx2 = gy2 = -1e9f;
            area = 0.0f;
        }
        s_box[t]  = make_float4(gx1, gy1, gx2, gy2);
        s_area[t] = area;
    }
    __syncthreads();

    const int TOT = (N + 1) >> 1;           // 2 anchors per thread
    int gid = blockIdx.x * blockDim.x + t;
    if (gid >= TOT) return;

    const int a0 = gid;
    const int a1 = gid + TOT;
    const bool has1 = (a1 < N);

    const float4* A4 = reinterpret_cast<const float4*>(anchors);
    const float4* D4 = reinterpret_cast<const float4*>(deltas);

    float4 A0 = A4[a0];
    float4 D0 = D4[a0];
    float4 A1 = has1 ? A4[a1] : A0;
    float4 D1 = has1 ? D4[a1] : D0;

    // ---- proposals (tolerance 1e-3: plain fp math is fine here) ----
    {
        float px = (A0.x + A0.z) * 0.5f;
        float py = (A0.y + A0.w) * 0.5f;
        float pw = (A0.z - A0.x) * 0.5f;
        float ph = (A0.w - A0.y) * 0.5f;
        float dw = fminf(D0.z, SCALE_CLAMP);
        float dh = fminf(D0.w, SCALE_CLAMP);
        float bx = px + pw * D0.x;
        float by = py + ph * D0.y;
        float bw = pw * expf(dw);
        float bh = ph * expf(dh);
        reinterpret_cast<float4*>(out)[a0] = make_float4(bx - bw, by - bh, bx + bw, by + bh);
    }
    if (has1) {
        float px = (A1.x + A1.z) * 0.5f;
        float py = (A1.y + A1.w) * 0.5f;
        float pw = (A1.z - A1.x) * 0.5f;
        float ph = (A1.w - A1.y) * 0.5f;
        float dw = fminf(D1.z, SCALE_CLAMP);
        float dh = fminf(D1.w, SCALE_CLAMP);
        float bx = px + pw * D1.x;
        float by = py + ph * D1.y;
        float bw = pw * expf(dw);
        float bh = ph * expf(dh);
        reinterpret_cast<float4*>(out)[a1] = make_float4(bx - bw, by - bh, bx + bw, by + bh);
    }

    // ---- IoU argmax over GT, division-free tracking ----
    // Track best as (inter_b, sA_b, c1_b, idx_b), where union_b = sA_b - inter_b
    // and c1_b = inter_b + union_b ≈ sA_b (approximate is fine: only affects
    // comparisons, which only matter outside the ~ulp tie window).
    // Comparison:  inter_j/union_j > inter_b/union_b
    //          <=>  inter_j * c1_b > inter_b * sA_j        (unions > 0)
    float area1_0 = __fmul_rn(__fsub_rn(A0.z, A0.x), __fsub_rn(A0.w, A0.y));
    float area1_1 = __fmul_rn(__fsub_rn(A1.z, A1.x), __fsub_rn(A1.w, A1.y));

    float ib0 = -1.0f, sab0 = 0.0f, c10 = 0.0f; int idx0 = 0;
    float ib1 = -1.0f, sab1 = 0.0f, c11 = 0.0f; int idx1 = 0;

    #pragma unroll 4
    for (int j = 0; j < M; j++) {
        float4 g = s_box[j];     // warp-uniform broadcast
        float a2 = s_area[j];
        // anchor 0
        {
            float x1 = fmaxf(A0.x, g.x);
            float y1 = fmaxf(A0.y, g.y);
            float x2 = fminf(A0.z, g.z);
            float y2 = fminf(A0.w, g.w);
            float xl = __fsub_rn(x2, x1);
            float yl = __fsub_rn(y2, y1);
            float inter = (xl > 0.0f && yl > 0.0f) ? __fmul_rn(xl, yl) : 0.0f;
            float sA = __fadd_rn(area1_0, a2);
            if (inter * c10 > ib0 * sA) {
                ib0 = inter; sab0 = sA; c10 = sA; idx0 = j;
            }
        }
        // anchor 1
        {
            float x1 = fmaxf(A1.x, g.x);
            float y1 = fmaxf(A1.y, g.y);
            float x2 = fminf(A1.z, g.z);
            float y2 = fminf(A1.w, g.w);
            float xl = __fsub_rn(x2, x1);
            float yl = __fsub_rn(y2, y1);
            float inter = (xl > 0.0f && yl > 0.0f) ? __fmul_rn(xl, yl) : 0.0f;
            float sA = __fadd_rn(area1_1, a2);
            if (inter * c11 > ib1 * sA) {
                ib1 = inter; sab1 = sA; c11 = sA; idx1 = j;
            }
        }
    }

    // ---- finalize: ONE exact IEEE division per anchor, classify, gather ----
    float* out2 = out + (size_t)4 * N;

    {
        float ub = __fsub_rn(sab0, ib0);          // reference: (a1+a2) - inter
        float q  = __fdiv_rn(ib0, ub);            // bit-exact match_quality
        float r0, r1, r2, r3, r4;
        if (q <= IOU_LOW) {
            r0 = r1 = r2 = r3 = r4 = -1.0f;
        } else if (q < IOU_HIGH) {
            r0 = r1 = r2 = r3 = r4 = NEUTRAL;
        } else {
            const float* p = gt + idx0 * 5;       // original (non-degenerate) row
            r0 = __ldg(p + 0); r1 = __ldg(p + 1); r2 = __ldg(p + 2);
            r3 = __ldg(p + 3); r4 = __ldg(p + 4);
        }
        float* o = out2 + (size_t)a0 * 5;
        o[0] = r0; o[1] = r1; o[2] = r2; o[3] = r3; o[4] = r4;
    }
    if (has1) {
        float ub = __fsub_rn(sab1, ib1);
        float q  = __fdiv_rn(ib1, ub);
        float r0, r1, r2, r3, r4;
        if (q <= IOU_LOW) {
            r0 = r1 = r2 = r3 = r4 = -1.0f;
        } else if (q < IOU_HIGH) {
            r0 = r1 = r2 = r3 = r4 = NEUTRAL;
        } else {
            const float* p = gt + idx1 * 5;
            r0 = __ldg(p + 0); r1 = __ldg(p + 1); r2 = __ldg(p + 2);
            r3 = __ldg(p + 3); r4 = __ldg(p + 4);
        }
        float* o = out2 + (size_t)a1 * 5;
        o[0] = r0; o[1] = r1; o[2] = r2; o[3] = r3; o[4] = r4;
    }
}

extern "C" void kernel_launch(void* const* d_in, const int* in_sizes, int n_in,
                              void* d_out, int out_size)
{
    const float* anchors = (const float*)d_in[0];
    const float* deltas  = (const float*)d_in[1];
    const float* gt      = (const float*)d_in[2];
    float* out = (float*)d_out;

    int N = in_sizes[0] / 4;
    int M = in_sizes[2] / 5;
    if (M > M_GT_MAX) M = M_GT_MAX;

    int TOT = (N + 1) / 2;
    int threads = 256;
    int blocks = (TOT + threads - 1) / threads;
    rpn_kernel<<<blocks, threads>>>(anchors, deltas, gt, out, N, M);
}